// round 11
// baseline (speedup 1.0000x reference)
#include <cuda_runtime.h>
#include <cuda_bf16.h>
#include <math.h>

#define S    2048
#define H    1024
#define NH   16
#define HD   64
#define H3   3072
#define E    8
#define II   4096
#define CAP  1024
#define NTOK S

typedef unsigned short u16;
typedef unsigned int   u32;

// ---------------- fp32 scratch ----------------
__device__ float g_qkv [S*H3];
__device__ float g_x1  [S*H];
__device__ float g_xn2 [S*H];
__device__ float g_G   [(size_t)E*CAP*II];
__device__ float g_U   [(size_t)E*CAP*II];
__device__ float g_Y   [E*CAP*H];

// bf16 hi/lo pre-split operands
__device__ u16 g_xnh [S*H],  g_xnl [S*H];
__device__ u16 g_atnh[S*H],  g_atnl[S*H];
__device__ u16 g_Xgh [E*CAP*H], g_Xgl [E*CAP*H];
__device__ u16 g_acth[(size_t)E*CAP*II], g_actl[(size_t)E*CAP*II];
__device__ u16 g_qwh [H3*H], g_qwl [H3*H];
__device__ u16 g_owh [H*H],  g_owl [H*H];
__device__ u16 g_wgh [(size_t)E*II*H], g_wgl [(size_t)E*II*H];
__device__ u16 g_wuh [(size_t)E*II*H], g_wul [(size_t)E*II*H];
__device__ u16 g_wdh [(size_t)E*H*II], g_wdl [(size_t)E*H*II];

// attention prep buffers
__device__ u16 g_Qh[NH*S*64], g_Ql[NH*S*64];
__device__ u16 g_Kh[NH*S*64], g_Kl[NH*S*64];
__device__ u32 g_Vh[NH*(S/2)*64], g_Vl[NH*(S/2)*64];

__device__ int   g_e1[NTOK], g_e2[NTOK];
__device__ float g_w1[NTOK], g_w2[NTOK];
__device__ int   g_slot1[NTOK], g_slot2[NTOK];
__device__ int   g_valid1[NTOK], g_valid2[NTOK];
__device__ int   g_tok[E*CAP];
__device__ int   g_count[E];
__device__ int   g_count_used[E];

// ---------------- helpers ----------------
__device__ __forceinline__ void split2_bf16(float f0, float f1,
                                            unsigned& hi, unsigned& lo) {
    __nv_bfloat16 h0 = __float2bfloat16_rn(f0);
    __nv_bfloat16 h1 = __float2bfloat16_rn(f1);
    float r0 = f0 - __bfloat162float(h0);
    float r1 = f1 - __bfloat162float(h1);
    __nv_bfloat16 l0 = __float2bfloat16_rn(r0);
    __nv_bfloat16 l1 = __float2bfloat16_rn(r1);
    hi = ((unsigned)__bfloat16_as_ushort(h1) << 16) | __bfloat16_as_ushort(h0);
    lo = ((unsigned)__bfloat16_as_ushort(l1) << 16) | __bfloat16_as_ushort(l0);
}

#define MMA_BF16(acc, a, b)                                               \
    asm volatile(                                                         \
        "mma.sync.aligned.m16n8k16.row.col.f32.bf16.bf16.f32 "            \
        "{%0,%1,%2,%3}, {%4,%5,%6,%7}, {%8,%9}, {%0,%1,%2,%3};"           \
        : "+f"(acc[0]), "+f"(acc[1]), "+f"(acc[2]), "+f"(acc[3])          \
        : "r"(a[0]), "r"(a[1]), "r"(a[2]), "r"(a[3]), "r"(b[0]), "r"(b[1]))

// ---------------- generic fp32 -> bf16 hi/lo split ----------------
__global__ void split_kernel(const float* __restrict__ in,
                             u16* __restrict__ hi, u16* __restrict__ lo, int n4) {
    int i = blockIdx.x * 256 + threadIdx.x;
    if (i >= n4) return;
    float4 v = ((const float4*)in)[i];
    unsigned h0, l0, h1, l1;
    split2_bf16(v.x, v.y, h0, l0);
    split2_bf16(v.z, v.w, h1, l1);
    ((uint2*)hi)[i] = make_uint2(h0, h1);
    ((uint2*)lo)[i] = make_uint2(l0, l1);
}

// ---------------- RMSNorm (fp32 out) ----------------
__global__ void rmsnorm_kernel(const float* __restrict__ x,
                               const float* __restrict__ w,
                               float* __restrict__ out) {
    int row = blockIdx.x;
    const float* xr = x + (size_t)row * H;
    float s = 0.f;
    for (int i = threadIdx.x; i < H; i += 256) { float v = xr[i]; s += v * v; }
    __shared__ float red[256];
    red[threadIdx.x] = s; __syncthreads();
    for (int off = 128; off > 0; off >>= 1) {
        if (threadIdx.x < off) red[threadIdx.x] += red[threadIdx.x + off];
        __syncthreads();
    }
    float inv = rsqrtf(red[0] / (float)H + 1e-6f);
    for (int i = threadIdx.x; i < H; i += 256)
        out[(size_t)row * H + i] = xr[i] * inv * w[i];
}

// ---------------- RMSNorm with fused split out ----------------
__global__ void rmsnorm_split_kernel(const float* __restrict__ x,
                                     const float* __restrict__ w,
                                     u16* __restrict__ oh, u16* __restrict__ ol) {
    int row = blockIdx.x;
    const float* xr = x + (size_t)row * H;
    float s = 0.f;
    for (int i = threadIdx.x; i < H; i += 256) { float v = xr[i]; s += v * v; }
    __shared__ float red[256];
    red[threadIdx.x] = s; __syncthreads();
    for (int off = 128; off > 0; off >>= 1) {
        if (threadIdx.x < off) red[threadIdx.x] += red[threadIdx.x + off];
        __syncthreads();
    }
    float inv = rsqrtf(red[0] / (float)H + 1e-6f);
    int i = threadIdx.x << 2;
    float4 v = *(const float4*)&xr[i];
    float4 wv = *(const float4*)&w[i];
    unsigned h0, l0, h1, l1;
    split2_bf16(v.x * inv * wv.x, v.y * inv * wv.y, h0, l0);
    split2_bf16(v.z * inv * wv.z, v.w * inv * wv.w, h1, l1);
    size_t o = (size_t)row * (H / 4) + threadIdx.x;
    ((uint2*)oh)[o] = make_uint2(h0, h1);
    ((uint2*)ol)[o] = make_uint2(l0, l1);
}

// ------- bf16x3 GEMM, pre-split operands: C = A*B^T (+residual) ------------------
// Identical structure to proven kernel; staging = direct uint4 loads (no cvt).
__global__ void __launch_bounds__(256)
gemm_sp_kernel(const u16* __restrict__ Ah, const u16* __restrict__ Al,
               const u16* __restrict__ Bh, const u16* __restrict__ Bl,
               float* __restrict__ C, const float* __restrict__ residual,
               int N, int K,
               size_t aStride, size_t bStride, size_t cStride,
               const int* __restrict__ counts) {
    int z = blockIdx.z;
    if (counts && (int)(blockIdx.y << 7) >= counts[z]) return;
    size_t aOff = (size_t)z * aStride + ((size_t)blockIdx.y << 7) * K;
    size_t bOff = (size_t)z * bStride + ((size_t)blockIdx.x << 7) * K;
    Ah += aOff; Al += aOff;
    Bh += bOff; Bl += bOff;
    C += (size_t)z * cStride;

    __shared__ unsigned sAh[2][8][136], sAl[2][8][136];
    __shared__ unsigned sBh[2][8][136], sBl[2][8][136];

    const int tid  = threadIdx.x;
    const int lrow = tid >> 1;           // 0..127
    const int kw   = (tid & 1) << 2;     // word 0 or 4
    const size_t rowK = (size_t)lrow * K + (kw << 1);  // u16 offset

    const int lane = tid & 31;
    const int wid  = tid >> 5;
    const int gid  = lane >> 2, tig = lane & 3;
    const int wm   = (wid >> 2) * 64;
    const int wn   = (wid & 3) * 32;

    float acc[4][4][4];
    #pragma unroll
    for (int i = 0; i < 4; i++)
        #pragma unroll
        for (int j = 0; j < 4; j++)
            #pragma unroll
            for (int r = 0; r < 4; r++) acc[i][j][r] = 0.f;

    uint4 rah = *(const uint4*)(Ah + rowK);
    uint4 ral = *(const uint4*)(Al + rowK);
    uint4 rbh = *(const uint4*)(Bh + rowK);
    uint4 rbl = *(const uint4*)(Bl + rowK);

    const int nk = K >> 4;

    // stage tile 0
    sAh[0][kw+0][lrow] = rah.x; sAh[0][kw+1][lrow] = rah.y;
    sAh[0][kw+2][lrow] = rah.z; sAh[0][kw+3][lrow] = rah.w;
    sAl[0][kw+0][lrow] = ral.x; sAl[0][kw+1][lrow] = ral.y;
    sAl[0][kw+2][lrow] = ral.z; sAl[0][kw+3][lrow] = ral.w;
    sBh[0][kw+0][lrow] = rbh.x; sBh[0][kw+1][lrow] = rbh.y;
    sBh[0][kw+2][lrow] = rbh.z; sBh[0][kw+3][lrow] = rbh.w;
    sBl[0][kw+0][lrow] = rbl.x; sBl[0][kw+1][lrow] = rbl.y;
    sBl[0][kw+2][lrow] = rbl.z; sBl[0][kw+3][lrow] = rbl.w;
    __syncthreads();

    for (int kt = 0; kt < nk; kt++) {
        const int cur = kt & 1;
        const bool more = (kt + 1 < nk);
        if (more) {
            size_t o = rowK + (size_t)(kt + 1) * 16;
            rah = *(const uint4*)(Ah + o);
            ral = *(const uint4*)(Al + o);
            rbh = *(const uint4*)(Bh + o);
            rbl = *(const uint4*)(Bl + o);
        }

        unsigned ah[4][4], al[4][4], bh[4][2], bl[4][2];
        #pragma unroll
        for (int mt = 0; mt < 4; mt++) {
            int m = wm + (mt << 4) + gid;
            ah[mt][0] = sAh[cur][tig    ][m];
            ah[mt][1] = sAh[cur][tig    ][m + 8];
            ah[mt][2] = sAh[cur][tig + 4][m];
            ah[mt][3] = sAh[cur][tig + 4][m + 8];
            al[mt][0] = sAl[cur][tig    ][m];
            al[mt][1] = sAl[cur][tig    ][m + 8];
            al[mt][2] = sAl[cur][tig + 4][m];
            al[mt][3] = sAl[cur][tig + 4][m + 8];
        }
        #pragma unroll
        for (int nt = 0; nt < 4; nt++) {
            int n = wn + (nt << 3) + gid;
            bh[nt][0] = sBh[cur][tig    ][n];
            bh[nt][1] = sBh[cur][tig + 4][n];
            bl[nt][0] = sBl[cur][tig    ][n];
            bl[nt][1] = sBl[cur][tig + 4][n];
        }
        #pragma unroll
        for (int mt = 0; mt < 4; mt++)
            #pragma unroll
            for (int nt = 0; nt < 4; nt++) {
                MMA_BF16(acc[mt][nt], al[mt], bh[nt]);
                MMA_BF16(acc[mt][nt], ah[mt], bl[nt]);
                MMA_BF16(acc[mt][nt], ah[mt], bh[nt]);
            }

        if (more) {
            const int nxt = 1 - cur;
            sAh[nxt][kw+0][lrow] = rah.x; sAh[nxt][kw+1][lrow] = rah.y;
            sAh[nxt][kw+2][lrow] = rah.z; sAh[nxt][kw+3][lrow] = rah.w;
            sAl[nxt][kw+0][lrow] = ral.x; sAl[nxt][kw+1][lrow] = ral.y;
            sAl[nxt][kw+2][lrow] = ral.z; sAl[nxt][kw+3][lrow] = ral.w;
            sBh[nxt][kw+0][lrow] = rbh.x; sBh[nxt][kw+1][lrow] = rbh.y;
            sBh[nxt][kw+2][lrow] = rbh.z; sBh[nxt][kw+3][lrow] = rbh.w;
            sBl[nxt][kw+0][lrow] = rbl.x; sBl[nxt][kw+1][lrow] = rbl.y;
            sBl[nxt][kw+2][lrow] = rbl.z; sBl[nxt][kw+3][lrow] = rbl.w;
        }
        __syncthreads();
    }

    const int rBase = (blockIdx.y << 7) + wm;
    const int cBase = (blockIdx.x << 7) + wn;
    #pragma unroll
    for (int mt = 0; mt < 4; mt++) {
        int r0 = rBase + (mt << 4) + gid;
        #pragma unroll
        for (int nt = 0; nt < 4; nt++) {
            int c = cBase + (nt << 3) + (tig << 1);
            size_t o0 = (size_t)r0 * N + c;
            size_t o1 = o0 + (size_t)8 * N;
            if (residual) {
                float2 q0 = *(const float2*)&residual[o0];
                float2 q1 = *(const float2*)&residual[o1];
                *(float2*)&C[o0] = make_float2(acc[mt][nt][0] + q0.x, acc[mt][nt][1] + q0.y);
                *(float2*)&C[o1] = make_float2(acc[mt][nt][2] + q1.x, acc[mt][nt][3] + q1.y);
            } else {
                *(float2*)&C[o0] = make_float2(acc[mt][nt][0], acc[mt][nt][1]);
                *(float2*)&C[o1] = make_float2(acc[mt][nt][2], acc[mt][nt][3]);
            }
        }
    }
}

// -------- prep: RoPE + split ----------------
__global__ void prep_qk_kernel(const float* __restrict__ qkv) {
    int s = blockIdx.x;
    const float* row = qkv + (size_t)s * H3;
    for (int rep = 0; rep < 4; rep++) {
        int it = threadIdx.x + (rep << 8);
        int part = it >> 9;
        int rem  = it & 511;
        int h    = rem >> 5;
        int d    = rem & 31;
        float invf = powf(10000.f, -2.f * (float)d / 64.f);
        float ang  = (float)s * invf;
        float sn, cs;
        sincosf(ang, &sn, &cs);
        const float* p = row + part * H + h * 64;
        float x0 = p[d], x1 = p[d + 32];
        float y0 = x0 * cs - x1 * sn;
        float y1 = x1 * cs + x0 * sn;
        if (part == 0) { y0 *= 0.125f; y1 *= 0.125f; }
        u16* Hb = part ? g_Kh : g_Qh;
        u16* Lb = part ? g_Kl : g_Ql;
        size_t base = ((size_t)h * S + s) * 64;
        __nv_bfloat16 h0 = __float2bfloat16_rn(y0);
        __nv_bfloat16 l0 = __float2bfloat16_rn(y0 - __bfloat162float(h0));
        Hb[base + d] = __bfloat16_as_ushort(h0);
        Lb[base + d] = __bfloat16_as_ushort(l0);
        __nv_bfloat16 h1 = __float2bfloat16_rn(y1);
        __nv_bfloat16 l1 = __float2bfloat16_rn(y1 - __bfloat162float(h1));
        Hb[base + d + 32] = __bfloat16_as_ushort(h1);
        Lb[base + d + 32] = __bfloat16_as_ushort(l1);
    }
}

__global__ void vtrans_kernel(const float* __restrict__ qkv) {
    int w = blockIdx.x;
    int h = blockIdx.y;
    int d = threadIdx.x;
    float v0 = qkv[(size_t)(2 * w)     * H3 + 2 * H + h * 64 + d];
    float v1 = qkv[(size_t)(2 * w + 1) * H3 + 2 * H + h * 64 + d];
    unsigned hi, lo;
    split2_bf16(v0, v1, hi, lo);
    size_t idx = ((size_t)h * (S / 2) + w) * 64 + d;
    g_Vh[idx] = hi;
    g_Vl[idx] = lo;
}

// -------- flash attention (tensor core), epilogue emits split attn ---------------
__global__ void __launch_bounds__(256)
flash2_kernel() {
    const int qt = gridDim.x - 1 - blockIdx.x;
    const int h  = blockIdx.y;
    const int qbase = qt << 7;

    __shared__ unsigned sKh[32][65], sKl[32][65];
    __shared__ unsigned sVh[32][65], sVl[32][65];

    const int tid  = threadIdx.x;
    const int wid  = tid >> 5;
    const int lane = tid & 31;
    const int gid  = lane >> 2, tig = lane & 3;
    const int m0   = wid << 4;

    const unsigned* Qh32 = (const unsigned*)g_Qh;
    const unsigned* Ql32 = (const unsigned*)g_Ql;
    const unsigned* Kh32 = (const unsigned*)g_Kh;
    const unsigned* Kl32 = (const unsigned*)g_Kl;

    unsigned qh_f[4][4], ql_f[4][4];
    {
        size_t r0 = ((size_t)h * S + qbase + m0 + gid) * 32;
        size_t r1 = r0 + 8 * 32;
        #pragma unroll
        for (int kk = 0; kk < 4; kk++) {
            int w = (kk << 3) + tig;
            qh_f[kk][0] = Qh32[r0 + w];     qh_f[kk][1] = Qh32[r1 + w];
            qh_f[kk][2] = Qh32[r0 + w + 4]; qh_f[kk][3] = Qh32[r1 + w + 4];
            ql_f[kk][0] = Ql32[r0 + w];     ql_f[kk][1] = Ql32[r1 + w];
            ql_f[kk][2] = Ql32[r0 + w + 4]; ql_f[kk][3] = Ql32[r1 + w + 4];
        }
    }

    float m_i[2] = {-1e30f, -1e30f};
    float l_i[2] = {0.f, 0.f};
    float oacc[8][4];
    #pragma unroll
    for (int i = 0; i < 8; i++)
        #pragma unroll
        for (int j = 0; j < 4; j++) oacc[i][j] = 0.f;

    const int nkt = 2 * qt + 2;
    for (int kt = 0; kt < nkt; kt++) {
        const int kbase = kt << 6;
        __syncthreads();
        #pragma unroll
        for (int i = 0; i < 8; i++) {
            int idx = tid + (i << 8);
            int r = idx >> 5, w = idx & 31;
            size_t gk = ((size_t)h * S + kbase + r) * 32 + w;
            sKh[w][r] = Kh32[gk];
            sKl[w][r] = Kl32[gk];
            int wv = idx >> 6, dv = idx & 63;
            size_t gv = ((size_t)h * (S / 2) + (kbase >> 1) + wv) * 64 + dv;
            sVh[wv][dv] = g_Vh[gv];
            sVl[wv][dv] = g_Vl[gv];
        }
        __syncthreads();

        float s[8][4];
        #pragma unroll
        for (int nt = 0; nt < 8; nt++)
            #pragma unroll
            for (int j = 0; j < 4; j++) s[nt][j] = 0.f;
        #pragma unroll
        for (int nt = 0; nt < 8; nt++) {
            int n = (nt << 3) + gid;
            #pragma unroll
            for (int kk = 0; kk < 4; kk++) {
                unsigned bh[2] = {sKh[(kk << 3) + tig][n], sKh[(kk << 3) + tig + 4][n]};
                unsigned bl[2] = {sKl[(kk << 3) + tig][n], sKl[(kk << 3) + tig + 4][n]};
                MMA_BF16(s[nt], ql_f[kk], bh);
                MMA_BF16(s[nt], qh_f[kk], bl);
                MMA_BF16(s[nt], qh_f[kk], bh);
            }
        }

        if (kbase + 63 > qbase + m0) {
            int r0 = qbase + m0 + gid, r1 = r0 + 8;
            #pragma unroll
            for (int nt = 0; nt < 8; nt++) {
                int c0 = kbase + (nt << 3) + (tig << 1);
                int c1 = c0 + 1;
                if (c0 > r0) s[nt][0] = -1e30f;
                if (c1 > r0) s[nt][1] = -1e30f;
                if (c0 > r1) s[nt][2] = -1e30f;
                if (c1 > r1) s[nt][3] = -1e30f;
            }
        }

        float rmax0 = -1e30f, rmax1 = -1e30f;
        #pragma unroll
        for (int nt = 0; nt < 8; nt++) {
            rmax0 = fmaxf(rmax0, fmaxf(s[nt][0], s[nt][1]));
            rmax1 = fmaxf(rmax1, fmaxf(s[nt][2], s[nt][3]));
        }
        #pragma unroll
        for (int off = 1; off <= 2; off <<= 1) {
            rmax0 = fmaxf(rmax0, __shfl_xor_sync(0xffffffffu, rmax0, off));
            rmax1 = fmaxf(rmax1, __shfl_xor_sync(0xffffffffu, rmax1, off));
        }
        float mnew0 = fmaxf(m_i[0], rmax0);
        float mnew1 = fmaxf(m_i[1], rmax1);
        float corr0 = __expf(m_i[0] - mnew0);
        float corr1 = __expf(m_i[1] - mnew1);
        float sum0 = 0.f, sum1 = 0.f;
        #pragma unroll
        for (int nt = 0; nt < 8; nt++) {
            s[nt][0] = __expf(s[nt][0] - mnew0); sum0 += s[nt][0];
            s[nt][1] = __expf(s[nt][1] - mnew0); sum0 += s[nt][1];
            s[nt][2] = __expf(s[nt][2] - mnew1); sum1 += s[nt][2];
            s[nt][3] = __expf(s[nt][3] - mnew1); sum1 += s[nt][3];
        }
        #pragma unroll
        for (int off = 1; off <= 2; off <<= 1) {
            sum0 += __shfl_xor_sync(0xffffffffu, sum0, off);
            sum1 += __shfl_xor_sync(0xffffffffu, sum1, off);
        }
        l_i[0] = l_i[0] * corr0 + sum0;
        l_i[1] = l_i[1] * corr1 + sum1;
        m_i[0] = mnew0;
        m_i[1] = mnew1;
        #pragma unroll
        for (int nt = 0; nt < 8; nt++) {
            oacc[nt][0] *= corr0; oacc[nt][1] *= corr0;
            oacc[nt][2] *= corr1; oacc[nt][3] *= corr1;
        }

        #pragma unroll
        for (int kk = 0; kk < 4; kk++) {
            unsigned ph[4], pl[4];
            split2_bf16(s[2*kk  ][0], s[2*kk  ][1], ph[0], pl[0]);
            split2_bf16(s[2*kk  ][2], s[2*kk  ][3], ph[1], pl[1]);
            split2_bf16(s[2*kk+1][0], s[2*kk+1][1], ph[2], pl[2]);
            split2_bf16(s[2*kk+1][2], s[2*kk+1][3], ph[3], pl[3]);
            #pragma unroll
            for (int ntd = 0; ntd < 8; ntd++) {
                int dcol = (ntd << 3) + gid;
                unsigned vh[2] = {sVh[(kk << 3) + tig][dcol], sVh[(kk << 3) + tig + 4][dcol]};
                unsigned vl[2] = {sVl[(kk << 3) + tig][dcol], sVl[(kk << 3) + tig + 4][dcol]};
                MMA_BF16(oacc[ntd], pl, vh);
                MMA_BF16(oacc[ntd], ph, vl);
                MMA_BF16(oacc[ntd], ph, vh);
            }
        }
    }

    float inv0 = 1.f / l_i[0];
    float inv1 = 1.f / l_i[1];
    int r0 = qbase + m0 + gid;
    #pragma unroll
    for (int ntd = 0; ntd < 8; ntd++) {
        int d = (ntd << 3) + (tig << 1);
        unsigned hw, lw;
        split2_bf16(oacc[ntd][0] * inv0, oacc[ntd][1] * inv0, hw, lw);
        *(unsigned*)&g_atnh[(size_t)r0 * H + h * 64 + d] = hw;
        *(unsigned*)&g_atnl[(size_t)r0 * H + h * 64 + d] = lw;
        split2_bf16(oacc[ntd][2] * inv1, oacc[ntd][3] * inv1, hw, lw);
        *(unsigned*)&g_atnh[(size_t)(r0 + 8) * H + h * 64 + d] = hw;
        *(unsigned*)&g_atnl[(size_t)(r0 + 8) * H + h * 64 + d] = lw;
    }
}

// ---------------- router ----------------
__global__ void router_kernel(const float* __restrict__ xn2, const float* __restrict__ rw) {
    int n = blockIdx.x;
    int tid = threadIdx.x;
    int e = tid >> 5, lane = tid & 31;
    const float* xr = xn2 + (size_t)n * H;
    const float* wr = rw + (size_t)e * H;
    float s = 0.f;
    for (int k = lane; k < H; k += 32) s += xr[k] * wr[k];
    #pragma unroll
    for (int off = 16; off > 0; off >>= 1) s += __shfl_down_sync(0xffffffff, s, off);
    __shared__ float logit[8];
    if (lane == 0) logit[e] = s;
    __syncthreads();
    if (tid == 0) {
        float mx = logit[0];
        for (int q = 1; q < 8; q++) mx = fmaxf(mx, logit[q]);
        float p[8]; float sum = 0.f;
        for (int q = 0; q < 8; q++) { p[q] = expf(logit[q] - mx); sum += p[q]; }
        for (int q = 0; q < 8; q++) p[q] /= sum;
        int b1 = 0;
        for (int q = 1; q < 8; q++) if (p[q] > p[b1]) b1 = q;
        int b2 = -1;
        for (int q = 0; q < 8; q++) {
            if (q == b1) continue;
            if (b2 < 0 || p[q] > p[b2]) b2 = q;
        }
        float ws = p[b1] + p[b2];
        g_e1[n] = b1; g_e2[n] = b2;
        g_w1[n] = p[b1] / ws; g_w2[n] = p[b2] / ws;
    }
}

// ---------------- slot assignment ----------------
__global__ void scan_kernel() {
    int w = threadIdx.x >> 5;
    int lane = threadIdx.x & 31;
    int base = 0;
    for (int c = 0; c < NTOK; c += 32) {
        int n = c + lane;
        int is1 = (g_e1[n] == w);
        int is2 = (g_e2[n] == w);
        int flag = is1 | is2;
        unsigned m = __ballot_sync(0xffffffff, flag);
        int pos = base + __popc(m & ((1u << lane) - 1u));
        if (flag) {
            int valid = pos < CAP;
            if (is1) { g_slot1[n] = pos; g_valid1[n] = valid; }
            else     { g_slot2[n] = pos; g_valid2[n] = valid; }
            if (valid) g_tok[w * CAP + pos] = n;
        }
        base += __popc(m);
    }
    if (lane == 0) {
        g_count[w] = base;
        g_count_used[w] = base < CAP ? base : CAP;
    }
}

// ---------------- gather with fused split ----------------
__global__ void gather_kernel(const float* __restrict__ xn2) {
    int e = blockIdx.x >> 10;
    int slot = blockIdx.x & 1023;
    if (slot >= g_count_used[e]) return;
    int n = g_tok[e * CAP + slot];
    float4 v = ((const float4*)(xn2 + (size_t)n * H))[threadIdx.x];
    unsigned h0, l0, h1, l1;
    split2_bf16(v.x, v.y, h0, l0);
    split2_bf16(v.z, v.w, h1, l1);
    size_t o = ((size_t)e * CAP + slot) * (H / 4) + threadIdx.x;
    ((uint2*)g_Xgh)[o] = make_uint2(h0, h1);
    ((uint2*)g_Xgl)[o] = make_uint2(l0, l1);
}

// ---------------- silu with fused split ----------------
__global__ void silu_kernel() {
    size_t i4 = (size_t)blockIdx.x * 256 + threadIdx.x;
    int e   = (int)(i4 / ((size_t)CAP * (II / 4)));
    int row = (int)((i4 / (II / 4)) % CAP);
    if (row >= g_count_used[e]) return;
    float4 g = ((const float4*)g_G)[i4];
    float4 u = ((const float4*)g_U)[i4];
    float a0 = g.x / (1.f + __expf(-g.x)) * u.x;
    float a1 = g.y / (1.f + __expf(-g.y)) * u.y;
    float a2 = g.z / (1.f + __expf(-g.z)) * u.z;
    float a3 = g.w / (1.f + __expf(-g.w)) * u.w;
    unsigned h0, l0, h1, l1;
    split2_bf16(a0, a1, h0, l0);
    split2_bf16(a2, a3, h1, l1);
    ((uint2*)g_acth)[i4] = make_uint2(h0, h1);
    ((uint2*)g_actl)[i4] = make_uint2(l0, l1);
}

// ---------------- combine ----------------
__global__ void combine_kernel(float* __restrict__ out) {
    int n = blockIdx.x;
    int e1 = g_e1[n], e2 = g_e2[n];
    int s1 = g_slot1[n], s2 = g_slot2[n];
    int v1 = g_valid1[n], v2 = g_valid2[n];
    float w1 = g_w1[n], w2 = g_w2[n];
    const float* y1 = g_Y + ((size_t)e1 * CAP + (v1 ? s1 : 0)) * H;
    const float* y2 = g_Y + ((size_t)e2 * CAP + (v2 ? s2 : 0)) * H;
    for (int h = threadIdx.x; h < H; h += 256) {
        float acc = g_x1[(size_t)n * H + h];
        if (v1) acc += w1 * y1[h];
        if (v2) acc += w2 * y2[h];
        out[(size_t)n * H + h] = acc;
    }
}

// ---------------- aux loss ----------------
__global__ void aux_kernel(float* __restrict__ out, int out_size) {
    if (out_size <= S * H) return;
    float m[8], mu = 0.f;
    for (int e = 0; e < 8; e++) { m[e] = (float)g_count[e] / (float)NTOK; mu += m[e]; }
    mu *= 0.125f;
    float var = 0.f;
    for (int e = 0; e < 8; e++) { float d = m[e] - mu; var += d * d; }
    var /= 7.f;
    out[S * H] = var * 8.f;
}

// ---------------- launch ----------------
extern "C" void kernel_launch(void* const* d_in, const int* in_sizes, int n_in,
                              void* d_out, int out_size) {
    const float* x     = (const float*)d_in[0];
    const float* anw   = (const float*)d_in[1];
    const float* qkv_w = (const float*)d_in[2];
    const float* o_w   = (const float*)d_in[3];
    const float* fnw   = (const float*)d_in[4];
    const float* rw    = (const float*)d_in[5];
    const float* wg    = (const float*)d_in[6];
    const float* wu    = (const float*)d_in[7];
    const float* wd    = (const float*)d_in[8];
    float* out = (float*)d_out;

    float *p_qkv, *p_x1, *p_xn2, *p_G, *p_U, *p_Y;
    u16 *p_xnh, *p_xnl, *p_atnh, *p_atnl, *p_Xgh, *p_Xgl, *p_acth, *p_actl;
    u16 *p_qwh, *p_qwl, *p_owh, *p_owl, *p_wgh, *p_wgl, *p_wuh, *p_wul, *p_wdh, *p_wdl;
    int* p_cu;
    cudaGetSymbolAddress((void**)&p_qkv, g_qkv);
    cudaGetSymbolAddress((void**)&p_x1,  g_x1);
    cudaGetSymbolAddress((void**)&p_xn2, g_xn2);
    cudaGetSymbolAddress((void**)&p_G,   g_G);
    cudaGetSymbolAddress((void**)&p_U,   g_U);
    cudaGetSymbolAddress((void**)&p_Y,   g_Y);
    cudaGetSymbolAddress((void**)&p_xnh, g_xnh);
    cudaGetSymbolAddress((void**)&p_xnl, g_xnl);
    cudaGetSymbolAddress((void**)&p_atnh,g_atnh);
    cudaGetSymbolAddress((void**)&p_atnl,g_atnl);
    cudaGetSymbolAddress((void**)&p_Xgh, g_Xgh);
    cudaGetSymbolAddress((void**)&p_Xgl, g_Xgl);
    cudaGetSymbolAddress((void**)&p_acth,g_acth);
    cudaGetSymbolAddress((void**)&p_actl,g_actl);
    cudaGetSymbolAddress((void**)&p_qwh, g_qwh);
    cudaGetSymbolAddress((void**)&p_qwl, g_qwl);
    cudaGetSymbolAddress((void**)&p_owh, g_owh);
    cudaGetSymbolAddress((void**)&p_owl, g_owl);
    cudaGetSymbolAddress((void**)&p_wgh, g_wgh);
    cudaGetSymbolAddress((void**)&p_wgl, g_wgl);
    cudaGetSymbolAddress((void**)&p_wuh, g_wuh);
    cudaGetSymbolAddress((void**)&p_wul, g_wul);
    cudaGetSymbolAddress((void**)&p_wdh, g_wdh);
    cudaGetSymbolAddress((void**)&p_wdl, g_wdl);
    cudaGetSymbolAddress((void**)&p_cu,  g_count_used);

    // weight splits (per launch; deterministic)
    split_kernel<<<(H3 * H / 4 + 255) / 256, 256>>>(qkv_w, p_qwh, p_qwl, H3 * H / 4);
    split_kernel<<<(H * H / 4 + 255) / 256, 256>>>(o_w, p_owh, p_owl, H * H / 4);
    const int nw = E * II * H / 4;
    split_kernel<<<(nw + 255) / 256, 256>>>(wg, p_wgh, p_wgl, nw);
    split_kernel<<<(nw + 255) / 256, 256>>>(wu, p_wuh, p_wul, nw);
    split_kernel<<<(nw + 255) / 256, 256>>>(wd, p_wdh, p_wdl, nw);

    // attention path
    rmsnorm_split_kernel<<<S, 256>>>(x, anw, p_xnh, p_xnl);
    gemm_sp_kernel<<<dim3(H3 / 128, S / 128, 1), 256>>>(
        p_xnh, p_xnl, p_qwh, p_qwl, p_qkv, nullptr, H3, H, 0, 0, 0, nullptr);
    prep_qk_kernel<<<S, 256>>>(p_qkv);
    vtrans_kernel<<<dim3(S / 2, NH), 64>>>(p_qkv);
    flash2_kernel<<<dim3(S / 128, NH), 256>>>();
    gemm_sp_kernel<<<dim3(H / 128, S / 128, 1), 256>>>(
        p_atnh, p_atnl, p_owh, p_owl, p_x1, x, H, H, 0, 0, 0, nullptr);

    // MoE path
    rmsnorm_kernel<<<S, 256>>>(p_x1, fnw, p_xn2);
    router_kernel<<<S, 256>>>(p_xn2, rw);
    scan_kernel<<<1, 256>>>();
    gather_kernel<<<E * CAP, 256>>>(p_xn2);
    gemm_sp_kernel<<<dim3(II / 128, CAP / 128, E), 256>>>(
        p_Xgh, p_Xgl, p_wgh, p_wgl, p_G, nullptr, II, H,
        (size_t)CAP * H, (size_t)II * H, (size_t)CAP * II, p_cu);
    gemm_sp_kernel<<<dim3(II / 128, CAP / 128, E), 256>>>(
        p_Xgh, p_Xgl, p_wuh, p_wul, p_U, nullptr, II, H,
        (size_t)CAP * H, (size_t)II * H, (size_t)CAP * II, p_cu);
    silu_kernel<<<E * CAP * II / 4 / 256, 256>>>();
    gemm_sp_kernel<<<dim3(H / 128, CAP / 128, E), 256>>>(
        p_acth, p_actl, p_wdh, p_wdl, p_Y, nullptr, H, II,
        (size_t)CAP * II, (size_t)H * II, (size_t)CAP * H, p_cu);
    combine_kernel<<<S, 256>>>(out);
    aux_kernel<<<1, 1>>>(out, out_size);
}